// round 13
// baseline (speedup 1.0000x reference)
#include <cuda_runtime.h>
#include <math.h>

// Problem constants
#define T_STEPS 256
#define BATCH   1024
#define SEG     64
#define HID     128
#define G4      512          // 4*HID
#define K0      192          // SEG + HID (layer 0 fused input)
#define K1      256          // HID + HID (layer 1)
#define R       8            // batch rows per CTA
#define NCTA    (BATCH / R)  // 128 CTAs
#define NTHR    512          // threads per CTA (4 gate groups x 128 j)
#define RPAD    12           // padded row stride (48B: float4 at +0 and +16 aligned)

// Per-gate weight planes: g_W0g[g][k][j] = W[n = g*128+j][k]
__device__ float g_W0g[4 * K0 * HID];   // 393 KB
__device__ float g_W1g[4 * K1 * HID];   // 524 KB
__device__ float g_b0[G4];
__device__ float g_b1[G4];

// ---------------------------------------------------------------------------
// Prep: fold prelstm into layer-0 input weights, split by gate.
//   k in [0,SEG)  : W0fold[n][k] = sum_h w_ih0[n][h] * pre_w[h][k]
//   k in [SEG,K0) : w_hh0[n][k-SEG]
// ---------------------------------------------------------------------------
__global__ void prep_kernel(
    const float* __restrict__ pre_w,  const float* __restrict__ pre_b,
    const float* __restrict__ w_ih0,  const float* __restrict__ w_hh0,
    const float* __restrict__ b_ih0,  const float* __restrict__ b_hh0,
    const float* __restrict__ w_ih1,  const float* __restrict__ w_hh1,
    const float* __restrict__ b_ih1,  const float* __restrict__ b_hh1)
{
    int idx = blockIdx.x * blockDim.x + threadIdx.x;
    int stride = gridDim.x * blockDim.x;

    for (int e = idx; e < 4 * K0 * HID; e += stride) {
        int g = e / (K0 * HID);
        int rem = e % (K0 * HID);
        int k = rem / HID;
        int j = rem % HID;
        int n = g * HID + j;
        float v;
        if (k < SEG) {
            float s = 0.f;
            #pragma unroll 8
            for (int h = 0; h < HID; h++)
                s += w_ih0[n * HID + h] * pre_w[h * SEG + k];
            v = s;
        } else {
            v = w_hh0[n * HID + (k - SEG)];
        }
        g_W0g[e] = v;
    }

    for (int e = idx; e < 4 * K1 * HID; e += stride) {
        int g = e / (K1 * HID);
        int rem = e % (K1 * HID);
        int k = rem / HID;
        int j = rem % HID;
        int n = g * HID + j;
        g_W1g[e] = (k < HID) ? w_ih1[n * HID + k] : w_hh1[n * HID + (k - HID)];
    }

    for (int n = idx; n < G4; n += stride) {
        float s = 0.f;
        for (int h = 0; h < HID; h++)
            s += w_ih0[n * HID + h] * pre_b[h];
        g_b0[n] = s + b_ih0[n] + b_hh0[n];
        g_b1[n] = b_ih1[n] + b_hh1[n];
    }
}

__device__ __forceinline__ float fsig(float x) {
    return __fdividef(1.f, 1.f + __expf(-x));
}
__device__ __forceinline__ float ftanh(float x) {
    return __fdividef(2.f, 1.f + __expf(-2.f * x)) - 1.f;
}

// ---------------------------------------------------------------------------
// Fused persistent LSTM. Grid: 128 CTAs x 512 threads.
// Thread (j = tid&127, g = tid>>7): hidden column j, gate g (i,f,g,o),
// ALL 8 rows in the matvec (scalar weight load -> 1 cache line per warp,
// zero redundancy across groups). Gate exchange via SMEM, state update of
// rows 2g..2g+1 per thread.
// ---------------------------------------------------------------------------
__global__ __launch_bounds__(NTHR, 1) void lstm_kernel(
    const float* __restrict__ x_in,   // [T, B, SEG]
    const float* __restrict__ h0in,   // [2, B, HID]
    const float* __restrict__ c0in,   // [2, B, HID]
    const float* __restrict__ post_w, // [1, HID]
    const float* __restrict__ post_b, // [1]
    float* __restrict__ out)          // pred[B] | h_t[2,B,H] | c_t[2,B,H]
{
    __shared__ __align__(16) float x_s[SEG * RPAD];    // [s][row]
    __shared__ __align__(16) float h0_s[HID * RPAD];   // [k][row]
    __shared__ __align__(16) float h1_s[HID * RPAD];   // [k][row]
    __shared__ __align__(16) float gsm[4 * R * HID];   // [gate][row][j]

    const int tid  = threadIdx.x;
    const int j    = tid & (HID - 1);
    const int g    = tid >> 7;          // gate id 0..3 (i,f,g,o)
    const int row0 = blockIdx.x * R;
    const int r0   = 2 * g;             // rows owned for state update

    float c0v[2], c1v[2], h0n[2], h1n[2];
    #pragma unroll
    for (int u = 0; u < 2; u++) {
        int b = row0 + r0 + u;
        c0v[u] = c0in[0 * BATCH * HID + b * HID + j];
        c1v[u] = c0in[1 * BATCH * HID + b * HID + j];
        h0_s[j * RPAD + r0 + u] = h0in[0 * BATCH * HID + b * HID + j];
        h1_s[j * RPAD + r0 + u] = h0in[1 * BATCH * HID + b * HID + j];
    }
    __syncthreads();

    const float* __restrict__ W0 = g_W0g + g * (K0 * HID) + j;
    const float* __restrict__ W1 = g_W1g + g * (K1 * HID) + j;
    const float bias0 = g_b0[g * HID + j];
    const float bias1 = g_b1[g * HID + j];

    for (int t = 0; t < T_STEPS; t++) {
        // Stage x_t: 512 floats, 1 per thread, k-major padded
        {
            int r = tid >> 6;          // 0..7
            int s = tid & 63;          // 0..63
            x_s[s * RPAD + r] = x_in[((long)t * BATCH + (row0 + r)) * SEG + s];
        }
        __syncthreads();

        // ================= layer 0 matvec (my gate, 8 rows) =================
        float acc[8];
        #pragma unroll
        for (int r = 0; r < 8; r++) acc[r] = bias0;

        #pragma unroll 8
        for (int k = 0; k < SEG; k++) {
            float w = W0[k * HID];
            float4 lo = *(const float4*)&x_s[k * RPAD];
            float4 hi = *(const float4*)&x_s[k * RPAD + 4];
            acc[0] = fmaf(w, lo.x, acc[0]);
            acc[1] = fmaf(w, lo.y, acc[1]);
            acc[2] = fmaf(w, lo.z, acc[2]);
            acc[3] = fmaf(w, lo.w, acc[3]);
            acc[4] = fmaf(w, hi.x, acc[4]);
            acc[5] = fmaf(w, hi.y, acc[5]);
            acc[6] = fmaf(w, hi.z, acc[6]);
            acc[7] = fmaf(w, hi.w, acc[7]);
        }
        #pragma unroll 8
        for (int k = 0; k < HID; k++) {
            float w = W0[(SEG + k) * HID];
            float4 lo = *(const float4*)&h0_s[k * RPAD];
            float4 hi = *(const float4*)&h0_s[k * RPAD + 4];
            acc[0] = fmaf(w, lo.x, acc[0]);
            acc[1] = fmaf(w, lo.y, acc[1]);
            acc[2] = fmaf(w, lo.z, acc[2]);
            acc[3] = fmaf(w, lo.w, acc[3]);
            acc[4] = fmaf(w, hi.x, acc[4]);
            acc[5] = fmaf(w, hi.y, acc[5]);
            acc[6] = fmaf(w, hi.z, acc[6]);
            acc[7] = fmaf(w, hi.w, acc[7]);
        }
        // activation (uniform per warp: g is constant within a warp)
        if (g == 2) {
            #pragma unroll
            for (int r = 0; r < 8; r++) acc[r] = ftanh(acc[r]);
        } else {
            #pragma unroll
            for (int r = 0; r < 8; r++) acc[r] = fsig(acc[r]);
        }
        #pragma unroll
        for (int r = 0; r < 8; r++)
            gsm[(g * R + r) * HID + j] = acc[r];
        __syncthreads();

        // state update rows 2g, 2g+1; publish new h0
        #pragma unroll
        for (int u = 0; u < 2; u++) {
            int r = r0 + u;
            float ig = gsm[(0 * R + r) * HID + j];
            float fg = gsm[(1 * R + r) * HID + j];
            float gg = gsm[(2 * R + r) * HID + j];
            float og = gsm[(3 * R + r) * HID + j];
            c0v[u] = fg * c0v[u] + ig * gg;
            h0n[u] = og * ftanh(c0v[u]);
            h0_s[j * RPAD + r] = h0n[u];
        }
        __syncthreads();

        // ================= layer 1 matvec =================
        #pragma unroll
        for (int r = 0; r < 8; r++) acc[r] = bias1;

        #pragma unroll 8
        for (int k = 0; k < HID; k++) {
            float w = W1[k * HID];
            float4 lo = *(const float4*)&h0_s[k * RPAD];      // new h0_t
            float4 hi = *(const float4*)&h0_s[k * RPAD + 4];
            acc[0] = fmaf(w, lo.x, acc[0]);
            acc[1] = fmaf(w, lo.y, acc[1]);
            acc[2] = fmaf(w, lo.z, acc[2]);
            acc[3] = fmaf(w, lo.w, acc[3]);
            acc[4] = fmaf(w, hi.x, acc[4]);
            acc[5] = fmaf(w, hi.y, acc[5]);
            acc[6] = fmaf(w, hi.z, acc[6]);
            acc[7] = fmaf(w, hi.w, acc[7]);
        }
        #pragma unroll 8
        for (int k = 0; k < HID; k++) {
            float w = W1[(HID + k) * HID];
            float4 lo = *(const float4*)&h1_s[k * RPAD];      // previous h1
            float4 hi = *(const float4*)&h1_s[k * RPAD + 4];
            acc[0] = fmaf(w, lo.x, acc[0]);
            acc[1] = fmaf(w, lo.y, acc[1]);
            acc[2] = fmaf(w, lo.z, acc[2]);
            acc[3] = fmaf(w, lo.w, acc[3]);
            acc[4] = fmaf(w, hi.x, acc[4]);
            acc[5] = fmaf(w, hi.y, acc[5]);
            acc[6] = fmaf(w, hi.z, acc[6]);
            acc[7] = fmaf(w, hi.w, acc[7]);
        }
        if (g == 2) {
            #pragma unroll
            for (int r = 0; r < 8; r++) acc[r] = ftanh(acc[r]);
        } else {
            #pragma unroll
            for (int r = 0; r < 8; r++) acc[r] = fsig(acc[r]);
        }
        #pragma unroll
        for (int r = 0; r < 8; r++)
            gsm[(g * R + r) * HID + j] = acc[r];
        __syncthreads();

        #pragma unroll
        for (int u = 0; u < 2; u++) {
            int r = r0 + u;
            float ig = gsm[(0 * R + r) * HID + j];
            float fg = gsm[(1 * R + r) * HID + j];
            float gg = gsm[(2 * R + r) * HID + j];
            float og = gsm[(3 * R + r) * HID + j];
            c1v[u] = fg * c1v[u] + ig * gg;
            h1n[u] = og * ftanh(c1v[u]);
            h1_s[j * RPAD + r] = h1n[u];
        }
        __syncthreads();   // protects h1_s and gsm for next iteration
    }

    // ---------------- outputs ----------------
    const int OH = BATCH;                    // h_t offset
    const int OC = BATCH + 2 * BATCH * HID;  // c_t offset
    #pragma unroll
    for (int u = 0; u < 2; u++) {
        int b = row0 + r0 + u;
        out[OH + 0 * BATCH * HID + b * HID + j] = h0n[u];
        out[OH + 1 * BATCH * HID + b * HID + j] = h1n[u];
        out[OC + 0 * BATCH * HID + b * HID + j] = c0v[u];
        out[OC + 1 * BATCH * HID + b * HID + j] = c1v[u];
    }

    // pred: warps 0..7, one warp per row, shuffle reduce over relu(h1)*post_w
    if (tid < 256) {
        int w    = tid >> 5;   // row 0..7
        int lane = tid & 31;
        float s = 0.f;
        #pragma unroll
        for (int jj = lane; jj < HID; jj += 32) {
            float hv = fmaxf(h1_s[jj * RPAD + w], 0.f);
            s += hv * post_w[jj];
        }
        #pragma unroll
        for (int off = 16; off; off >>= 1)
            s += __shfl_xor_sync(0xffffffffu, s, off);
        if (lane == 0)
            out[row0 + w] = s + post_b[0];
    }
}

extern "C" void kernel_launch(void* const* d_in, const int* in_sizes, int n_in,
                              void* d_out, int out_size)
{
    const float* x_in   = (const float*)d_in[0];
    const float* h0     = (const float*)d_in[1];
    const float* c0     = (const float*)d_in[2];
    const float* pre_w  = (const float*)d_in[3];
    const float* pre_b  = (const float*)d_in[4];
    const float* w_ih0  = (const float*)d_in[5];
    const float* w_hh0  = (const float*)d_in[6];
    const float* b_ih0  = (const float*)d_in[7];
    const float* b_hh0  = (const float*)d_in[8];
    const float* w_ih1  = (const float*)d_in[9];
    const float* w_hh1  = (const float*)d_in[10];
    const float* b_ih1  = (const float*)d_in[11];
    const float* b_hh1  = (const float*)d_in[12];
    const float* post_w = (const float*)d_in[13];
    const float* post_b = (const float*)d_in[14];
    float* out = (float*)d_out;

    prep_kernel<<<192, 256>>>(pre_w, pre_b, w_ih0, w_hh0, b_ih0, b_hh0,
                              w_ih1, w_hh1, b_ih1, b_hh1);
    lstm_kernel<<<NCTA, NTHR>>>(x_in, h0, c0, post_w, post_b, out);
}

// round 15
// speedup vs baseline: 1.3517x; 1.3517x over previous
#include <cuda_runtime.h>
#include <cuda_bf16.h>
#include <math.h>

// ---------------------------------------------------------------------------
// Problem constants
// ---------------------------------------------------------------------------
#define T_STEPS 256
#define BATCH   1024
#define SEG     64
#define HID     128
#define BH      (BATCH * HID)

#define GRP_ROWS 64            // batch rows per rowgroup
#define NGRP     16
#define PSLC     8             // j-slice CTAs per rowgroup
#define JS       16            // j columns per CTA
#define NCOLS    64            // gate cols per CTA (ncol = 4*jj+gate)
#define NCTA     (NGRP * PSLC) // 128
#define NTHR     512

// K space (global k): [0,64) W0x(folded) | [64,192) W0h | [192,320) W1x(h0) | [320,448) W1h(h1)
#define KTOT     448
#define KP_TOT   224           // u32 kpairs
#define NKT      28            // 16-k tiles total (12 layer0 + 16 layer1)
#define AST      164           // A row stride in u32 (mod 32 == 4 -> conflict-free)
#define BST      228           // B row stride in u32
#define GST      68            // gate buf row stride in floats

// SMEM layout (u32 units): 3 A planes + B-hi + G + bias
#define S_A0     0
#define S_A1     (GRP_ROWS * AST)        // 10496
#define S_A2     (2 * GRP_ROWS * AST)    // 20992
#define S_BHI    (3 * GRP_ROWS * AST)    // 31488
#define S_G      (S_BHI + NCOLS * BST)   // 46080
#define S_BIAS   (S_G + GRP_ROWS * GST)  // 50432
#define SMEM_U32 (S_BIAS + 2 * NCOLS)    // 50560
#define SMEM_BYTES (SMEM_U32 * 4)        // 202240

// ---------------------------------------------------------------------------
// Global scratch
// ---------------------------------------------------------------------------
__device__ float    g_Wfull[4 * HID * KTOT];          // [n][k] full fp32 weights
__device__ unsigned g_BwHi[PSLC][NCOLS * BST];        // hi plane, SMEM layout
__device__ uint4    g_Bfrag[2][PSLC][4][NKT][32];     // mid(0)/lo(1), fragment-major
__device__ float    g_bias[PSLC][2][NCOLS];
__device__ uint2    g_hbuf[2][NGRP][GRP_ROWS][HID];   // {hi<<16|mid, lo}
__device__ int      g_ctr[NGRP];

// ---------------------------------------------------------------------------
// helpers
// ---------------------------------------------------------------------------
__device__ __forceinline__ unsigned pack_bf(float e0, float e1) {
    unsigned lo = (unsigned)__bfloat16_as_ushort(__float2bfloat16_rn(e0));
    unsigned hi = (unsigned)__bfloat16_as_ushort(__float2bfloat16_rn(e1));
    return (hi << 16) | lo;
}
// 3-way split: v = f(s0) + f(s1) + f(s2) + O(2^-25 v)
__device__ __forceinline__ void split3(float v, float& s0, float& s1, float& s2) {
    __nv_bfloat16 q0 = __float2bfloat16_rn(v);
    s0 = __bfloat162float(q0);
    float r = v - s0;
    __nv_bfloat16 q1 = __float2bfloat16_rn(r);
    s1 = __bfloat162float(q1);
    s2 = r - s1;
}
__device__ __forceinline__ float fsig(float x) {
    return __fdividef(1.f, 1.f + __expf(-x));
}
__device__ __forceinline__ float ftanh(float x) {
    return __fdividef(2.f, 1.f + __expf(-2.f * x)) - 1.f;
}
__device__ __forceinline__ void mma16816(float* c,
    unsigned a0, unsigned a1, unsigned a2, unsigned a3,
    unsigned b0, unsigned b1)
{
    asm volatile(
        "mma.sync.aligned.m16n8k16.row.col.f32.bf16.bf16.f32 "
        "{%0,%1,%2,%3}, {%4,%5,%6,%7}, {%8,%9}, {%0,%1,%2,%3};"
        : "+f"(c[0]), "+f"(c[1]), "+f"(c[2]), "+f"(c[3])
        : "r"(a0), "r"(a1), "r"(a2), "r"(a3), "r"(b0), "r"(b1));
}

// ---------------------------------------------------------------------------
// prep1: full-precision fused weights + biases + barrier reset
// ---------------------------------------------------------------------------
__global__ void prep1_kernel(
    const float* __restrict__ pre_w,  const float* __restrict__ pre_b,
    const float* __restrict__ w_ih0,  const float* __restrict__ w_hh0,
    const float* __restrict__ b_ih0,  const float* __restrict__ b_hh0,
    const float* __restrict__ w_ih1,  const float* __restrict__ w_hh1,
    const float* __restrict__ b_ih1,  const float* __restrict__ b_hh1)
{
    int idx = blockIdx.x * blockDim.x + threadIdx.x;
    int stride = gridDim.x * blockDim.x;

    if (idx < NGRP) g_ctr[idx] = 0;

    for (int e = idx; e < 4 * HID * KTOT; e += stride) {
        int n = e / KTOT;
        int k = e % KTOT;
        float v;
        if (k < 64) {
            float s = 0.f;
            #pragma unroll 8
            for (int h = 0; h < HID; h++)
                s += w_ih0[n * HID + h] * pre_w[h * SEG + k];
            v = s;
        } else if (k < 192) {
            v = w_hh0[n * HID + (k - 64)];
        } else if (k < 320) {
            v = w_ih1[n * HID + (k - 192)];
        } else {
            v = w_hh1[n * HID + (k - 320)];
        }
        g_Wfull[e] = v;
    }

    for (int e = idx; e < PSLC * NCOLS; e += stride) {
        int js   = e / NCOLS;
        int ncol = e % NCOLS;
        int n    = (ncol & 3) * HID + js * JS + (ncol >> 2);
        float s = 0.f;
        for (int h = 0; h < HID; h++)
            s += w_ih0[n * HID + h] * pre_b[h];
        g_bias[js][0][ncol] = s + b_ih0[n] + b_hh0[n];
        g_bias[js][1][ncol] = b_ih1[n] + b_hh1[n];
    }
}

// ---------------------------------------------------------------------------
// prep2: build hi plane (SMEM layout) + mid/lo fragment-major planes
// ---------------------------------------------------------------------------
__device__ __forceinline__ float wterm(int n, int k, int pl) {
    // pl: 0 = mid, 1 = lo component of the 3-way split
    float v = g_Wfull[n * KTOT + k];
    float s0, s1, s2;
    split3(v, s0, s1, s2);
    return (pl == 0) ? s1 : s2;
}

__global__ void prep2_kernel()
{
    int idx = blockIdx.x * blockDim.x + threadIdx.x;
    int stride = gridDim.x * blockDim.x;

    // hi plane
    for (int e = idx; e < PSLC * NCOLS * KP_TOT; e += stride) {
        int js   = e / (NCOLS * KP_TOT);
        int rem  = e % (NCOLS * KP_TOT);
        int ncol = rem / KP_TOT;
        int kp   = rem % KP_TOT;
        int n    = (ncol & 3) * HID + js * JS + (ncol >> 2);
        float v0 = g_Wfull[n * KTOT + 2 * kp];
        float v1 = g_Wfull[n * KTOT + 2 * kp + 1];
        float a, b, c;
        float h0, h1;
        split3(v0, h0, a, b);
        split3(v1, h1, a, c);
        g_BwHi[js][ncol * BST + kp] = pack_bf(h0, h1);
    }

    // fragment planes: [pl][js][wn][kt][lane] -> 4 u32
    for (int e = idx; e < 2 * PSLC * 4 * NKT * 32; e += stride) {
        int lane = e & 31;
        int t1   = e >> 5;
        int kt   = t1 % NKT;  t1 /= NKT;
        int wn   = t1 % 4;    t1 /= 4;
        int js   = t1 % PSLC;
        int pl   = t1 / PSLC;
        int fg   = lane >> 2;
        int fq   = lane & 3;
        int kp0  = 8 * kt + fq;
        int kp1  = kp0 + 4;
        int c0   = 16 * wn + fg;
        int c1   = c0 + 8;
        int n0   = (c0 & 3) * HID + js * JS + (c0 >> 2);
        int n1   = (c1 & 3) * HID + js * JS + (c1 >> 2);
        uint4 u;
        u.x = pack_bf(wterm(n0, 2 * kp0, pl), wterm(n0, 2 * kp0 + 1, pl));
        u.y = pack_bf(wterm(n0, 2 * kp1, pl), wterm(n0, 2 * kp1 + 1, pl));
        u.z = pack_bf(wterm(n1, 2 * kp0, pl), wterm(n1, 2 * kp0 + 1, pl));
        u.w = pack_bf(wterm(n1, 2 * kp1, pl), wterm(n1, 2 * kp1 + 1, pl));
        g_Bfrag[pl][js][wn][kt][lane] = u;
    }
}

// ---------------------------------------------------------------------------
// one layer's 6-term mma sweep
// ---------------------------------------------------------------------------
__device__ __forceinline__ void do_layer(
    const unsigned* __restrict__ sA0, const unsigned* __restrict__ sA1,
    const unsigned* __restrict__ sA2, const unsigned* __restrict__ sBhi,
    const uint4* __restrict__ fpm, const uint4* __restrict__ fpl,
    int mr, int fg, int fq, int wn,
    int akp_base, int bkt_base, int nkt,
    float* acc0, float* acc1)
{
    uint4 bm = fpm[bkt_base * 32];
    uint4 bl = fpl[bkt_base * 32];
    #pragma unroll 4
    for (int kt = 0; kt < nkt; kt++) {
        uint4 bm_n = bm, bl_n = bl;
        if (kt + 1 < nkt) {
            bm_n = fpm[(bkt_base + kt + 1) * 32];
            bl_n = fpl[(bkt_base + kt + 1) * 32];
        }
        int akp = akp_base + 8 * kt;
        int ra = (mr + fg) * AST + akp + fq;
        int rb = (mr + fg + 8) * AST + akp + fq;
        unsigned a00 = sA0[ra], a01 = sA0[rb], a02 = sA0[ra + 4], a03 = sA0[rb + 4];
        unsigned a10 = sA1[ra], a11 = sA1[rb], a12 = sA1[ra + 4], a13 = sA1[rb + 4];
        unsigned a20 = sA2[ra], a21 = sA2[rb], a22 = sA2[ra + 4], a23 = sA2[rb + 4];
        int kb = 8 * (bkt_base + kt) + fq;
        {
            int nb = 16 * wn;
            unsigned bh0 = sBhi[(nb + fg) * BST + kb];
            unsigned bh1 = sBhi[(nb + fg) * BST + kb + 4];
            mma16816(acc0, a00, a01, a02, a03, bh0, bh1);
            mma16816(acc0, a10, a11, a12, a13, bh0, bh1);
            mma16816(acc0, a20, a21, a22, a23, bh0, bh1);
            mma16816(acc0, a00, a01, a02, a03, bm.x, bm.y);
            mma16816(acc0, a10, a11, a12, a13, bm.x, bm.y);
            mma16816(acc0, a00, a01, a02, a03, bl.x, bl.y);
        }
        {
            int nb = 16 * wn + 8;
            unsigned bh0 = sBhi[(nb + fg) * BST + kb];
            unsigned bh1 = sBhi[(nb + fg) * BST + kb + 4];
            mma16816(acc1, a00, a01, a02, a03, bh0, bh1);
            mma16816(acc1, a10, a11, a12, a13, bh0, bh1);
            mma16816(acc1, a20, a21, a22, a23, bh0, bh1);
            mma16816(acc1, a00, a01, a02, a03, bm.z, bm.w);
            mma16816(acc1, a10, a11, a12, a13, bm.z, bm.w);
            mma16816(acc1, a00, a01, a02, a03, bl.z, bl.w);
        }
        bm = bm_n; bl = bl_n;
    }
}

// ---------------------------------------------------------------------------
// Persistent tensor-core LSTM
// ---------------------------------------------------------------------------
__global__ __launch_bounds__(NTHR, 1) void lstm_kernel(
    const float* __restrict__ x_in,
    const float* __restrict__ h0in,
    const float* __restrict__ c0in,
    const float* __restrict__ post_w,
    const float* __restrict__ post_b,
    float* __restrict__ out)
{
    extern __shared__ unsigned smem_u[];
    unsigned* sA0  = smem_u + S_A0;
    unsigned* sA1  = smem_u + S_A1;
    unsigned* sA2  = smem_u + S_A2;
    unsigned* sBhi = smem_u + S_BHI;
    float*    sG   = (float*)(smem_u + S_G);
    float*    sBias= (float*)(smem_u + S_BIAS);

    const int tid  = threadIdx.x;
    const int grp  = blockIdx.x >> 3;
    const int js   = blockIdx.x & 7;
    const int wid  = tid >> 5;
    const int lane = tid & 31;
    const int wm   = wid & 3;
    const int wn   = wid >> 2;
    const int mr   = 16 * wm;
    const int fg   = lane >> 2;
    const int fq   = lane & 3;
    const int brow0 = grp * GRP_ROWS;

    for (int i = tid; i < NCOLS * BST; i += NTHR)
        sBhi[i] = g_BwHi[js][i];
    if (tid < 2 * NCOLS)
        sBias[tid] = g_bias[js][tid >> 6][tid & 63];

    // initial h0/h1 -> A planes (kpair bases 32 / 96)
    #pragma unroll
    for (int l = 0; l < 2; l++) {
        int base = (l == 0) ? 32 : 96;
        for (int e = tid; e < 4096; e += NTHR) {
            int r = e >> 6, m = e & 63;
            const float2 v = *(const float2*)&h0in[l * BH + (brow0 + r) * HID + 2 * m];
            float x0, x1, x2, y0, y1, y2;
            split3(v.x, x0, x1, x2);
            split3(v.y, y0, y1, y2);
            sA0[r * AST + base + m] = pack_bf(x0, y0);
            sA1[r * AST + base + m] = pack_bf(x1, y1);
            sA2[r * AST + base + m] = pack_bf(x2, y2);
        }
    }

    float c0v[2], c1v[2], h0n[2], h1n[2];
    #pragma unroll
    for (int u = 0; u < 2; u++) {
        int p = tid + NTHR * u;
        int jj = p >> 6, r = p & 63;
        int j = js * JS + jj;
        int b = brow0 + r;
        c0v[u] = c0in[0 * BH + b * HID + j];
        c1v[u] = c0in[1 * BH + b * HID + j];
        h0n[u] = h0in[0 * BH + b * HID + j];
        h1n[u] = h0in[1 * BH + b * HID + j];
    }
    __syncthreads();

    const uint4* fpm = &g_Bfrag[0][js][wn][0][lane];
    const uint4* fpl = &g_Bfrag[1][js][wn][0][lane];

    int phase = 0;

    for (int t = 0; t < T_STEPS; t++) {
        // stage x_t -> A kpairs 0..31
        for (int e = tid; e < 2048; e += NTHR) {
            int r = e >> 5, kp = e & 31;
            const float2 xv = *(const float2*)&x_in[((long)t * BATCH + brow0 + r) * SEG + 2 * kp];
            float x0, x1, x2, y0, y1, y2;
            split3(xv.x, x0, x1, x2);
            split3(xv.y, y0, y1, y2);
            sA0[r * AST + kp] = pack_bf(x0, y0);
            sA1[r * AST + kp] = pack_bf(x1, y1);
            sA2[r * AST + kp] = pack_bf(x2, y2);
        }
        __syncthreads();

        // ---- layer 0 ----
        {
            float acc0[4] = {0, 0, 0, 0}, acc1[4] = {0, 0, 0, 0};
            do_layer(sA0, sA1, sA2, sBhi, fpm, fpl, mr, fg, fq, wn,
                     0, 0, 12, acc0, acc1);
            int nb0 = 16 * wn, nb1 = 16 * wn + 8;
            *(float2*)&sG[(mr + fg) * GST + nb0 + 2 * fq]     = make_float2(acc0[0], acc0[1]);
            *(float2*)&sG[(mr + fg + 8) * GST + nb0 + 2 * fq] = make_float2(acc0[2], acc0[3]);
            *(float2*)&sG[(mr + fg) * GST + nb1 + 2 * fq]     = make_float2(acc1[0], acc1[1]);
            *(float2*)&sG[(mr + fg + 8) * GST + nb1 + 2 * fq] = make_float2(acc1[2], acc1[3]);
        }
        __syncthreads();

        #pragma unroll
        for (int u = 0; u < 2; u++) {
            int p = tid + NTHR * u;
            int jj = p >> 6, r = p & 63;
            float4 gv = *(const float4*)&sG[r * GST + 4 * jj];
            float4 bb = *(const float4*)&sBias[4 * jj];
            float ig  = fsig(gv.x + bb.x);
            float fgt = fsig(gv.y + bb.y);
            float gg  = ftanh(gv.z + bb.z);
            float og  = fsig(gv.w + bb.w);
            c0v[u] = fgt * c0v[u] + ig * gg;
            h0n[u] = og * ftanh(c0v[u]);
            float s0, s1, s2;
            split3(h0n[u], s0, s1, s2);
            uint2 pk;
            pk.x = ((unsigned)__bfloat16_as_ushort(__float2bfloat16_rn(s0)) << 16)
                 | (unsigned)__bfloat16_as_ushort(__float2bfloat16_rn(s1));
            pk.y = (unsigned)__bfloat16_as_ushort(__float2bfloat16_rn(s2));
            g_hbuf[0][grp][r][js * JS + jj] = pk;
        }
        __threadfence();
        __syncthreads();
        phase++;
        if (tid == 0) {
            atomicAdd(&g_ctr[grp], 1);
            while (*(volatile int*)&g_ctr[grp] < phase * PSLC) __nanosleep(64);
        }
        __syncthreads();

        // gather h0 -> A kpairs 32..95
        for (int e = tid; e < 4096; e += NTHR) {
            int r = e >> 6, m = e & 63;
            uint4 q = __ldcg((const uint4*)&g_hbuf[0][grp][r][2 * m]);
            sA0[r * AST + 32 + m] = (q.z & 0xffff0000u) | (q.x >> 16);
            sA1[r * AST + 32 + m] = ((q.z & 0xffffu) << 16) | (q.x & 0xffffu);
            sA2[r * AST + 32 + m] = ((q.w & 0xffffu) << 16) | (q.y & 0xffffu);
        }
        __syncthreads();

        // ---- layer 1 ----
        {
            float acc0[4] = {0, 0, 0, 0}, acc1[4] = {0, 0, 0, 0};
            do_layer(sA0, sA1, sA2, sBhi, fpm, fpl, mr, fg, fq, wn,
                     32, 12, 16, acc0, acc1);
            int nb0 = 16 * wn, nb1 = 16 * wn + 8;
            *(float2*)&sG[(mr + fg) * GST + nb0 + 2 * fq]     = make_float2(acc0[0], acc0[1]);
            *(float2*)&sG[(mr + fg + 8) * GST + nb0 + 2 * fq] = make_float2(acc0[2], acc0[3]);
            *(float2*)&sG[(mr + fg) * GST + nb1 + 2 * fq]     = make_float2(acc1[0], acc1[1]);
            *(float2*)&sG[(mr + fg + 8) * GST + nb1 + 2 * fq] = make_float2(acc1[2], acc1[3]);
        }
        __syncthreads();

        #pragma unroll
        for (int u = 0; u < 2; u++) {
            int p = tid + NTHR * u;
            int jj = p >> 6, r = p & 63;
            float4 gv = *(const float4*)&sG[r * GST + 4 * jj];
            float4 bb = *(const float4*)&sBias[64 + 4 * jj];
            float ig  = fsig(gv.x + bb.x);
            float fgt = fsig(gv.y + bb.y);
            float gg  = ftanh(gv.z + bb.z);
            float og  = fsig(gv.w + bb.w);
            c1v[u] = fgt * c1v[u] + ig * gg;
            h1n[u] = og * ftanh(c1v[u]);
            float s0, s1, s2;
            split3(h1n[u], s0, s1, s2);
            uint2 pk;
            pk.x = ((unsigned)__bfloat16_as_ushort(__float2bfloat16_rn(s0)) << 16)
                 | (unsigned)__bfloat16_as_ushort(__float2bfloat16_rn(s1));
            pk.y = (unsigned)__bfloat16_as_ushort(__float2bfloat16_rn(s2));
            g_hbuf[1][grp][r][js * JS + jj] = pk;
        }
        __threadfence();
        __syncthreads();
        phase++;
        if (tid == 0) {
            atomicAdd(&g_ctr[grp], 1);
            while (*(volatile int*)&g_ctr[grp] < phase * PSLC) __nanosleep(64);
        }
        __syncthreads();

        // gather h1 -> A kpairs 96..159
        for (int e = tid; e < 4096; e += NTHR) {
            int r = e >> 6, m = e & 63;
            uint4 q = __ldcg((const uint4*)&g_hbuf[1][grp][r][2 * m]);
            sA0[r * AST + 96 + m] = (q.z & 0xffff0000u) | (q.x >> 16);
            sA1[r * AST + 96 + m] = ((q.z & 0xffffu) << 16) | (q.x & 0xffffu);
            sA2[r * AST + 96 + m] = ((q.w & 0xffffu) << 16) | (q.y & 0xffffu);
        }
        // next iteration's post-x-staging __syncthreads orders these writes
    }

    // ---------------- outputs ----------------
    const int OH = BATCH;
    const int OC = BATCH + 2 * BH;
    #pragma unroll
    for (int u = 0; u < 2; u++) {
        int p = tid + NTHR * u;
        int jj = p >> 6, r = p & 63;
        int j = js * JS + jj;
        int b = brow0 + r;
        out[OH + 0 * BH + b * HID + j] = h0n[u];
        out[OH + 1 * BH + b * HID + j] = h1n[u];
        out[OC + 0 * BH + b * HID + j] = c0v[u];
        out[OC + 1 * BH + b * HID + j] = c1v[u];
    }

    // pred (js==0 CTA; hbuf[1] complete after final barrier)
    if (js == 0 && tid < GRP_ROWS) {
        int r = tid;
        float s = 0.f;
        #pragma unroll 8
        for (int m = 0; m < HID; m++) {
            uint2 pk = __ldcg(&g_hbuf[1][grp][r][m]);
            float hv = __bfloat162float(__ushort_as_bfloat16((unsigned short)(pk.x >> 16)))
                     + __bfloat162float(__ushort_as_bfloat16((unsigned short)(pk.x & 0xffffu)))
                     + __bfloat162float(__ushort_as_bfloat16((unsigned short)(pk.y & 0xffffu)));
            s += fmaxf(hv, 0.f) * post_w[m];
        }
        out[brow0 + r] = s + post_b[0];
    }
}

extern "C" void kernel_launch(void* const* d_in, const int* in_sizes, int n_in,
                              void* d_out, int out_size)
{
    const float* x_in   = (const float*)d_in[0];
    const float* h0     = (const float*)d_in[1];
    const float* c0     = (const float*)d_in[2];
    const float* pre_w  = (const float*)d_in[3];
    const float* pre_b  = (const float*)d_in[4];
    const float* w_ih0  = (const float*)d_in[5];
    const float* w_hh0  = (const float*)d_in[6];
    const float* b_ih0  = (const float*)d_in[7];
    const float* b_hh0  = (const float*)d_in[8];
    const float* w_ih1  = (const float*)d_in[9];
    const float* w_hh1  = (const float*)d_in[10];
    const float* b_ih1  = (const float*)d_in[11];
    const float* b_hh1  = (const float*)d_in[12];
    const float* post_w = (const float*)d_in[13];
    const float* post_b = (const float*)d_in[14];
    float* out = (float*)d_out;

    static int attr_set = 0;
    if (!attr_set) {
        cudaFuncSetAttribute(lstm_kernel,
                             cudaFuncAttributeMaxDynamicSharedMemorySize,
                             SMEM_BYTES);
        attr_set = 1;
    }

    prep1_kernel<<<192, 256>>>(pre_w, pre_b, w_ih0, w_hh0, b_ih0, b_hh0,
                               w_ih1, w_hh1, b_ih1, b_hh1);
    prep2_kernel<<<192, 256>>>();
    lstm_kernel<<<NCTA, NTHR, SMEM_BYTES>>>(x_in, h0, c0, post_w, post_b, out);
}

// round 16
// speedup vs baseline: 1.6304x; 1.2062x over previous
#include <cuda_runtime.h>
#include <cuda_bf16.h>
#include <math.h>

// ---------------------------------------------------------------------------
// Problem constants
// ---------------------------------------------------------------------------
#define T_STEPS 256
#define BATCH   1024
#define SEG     64
#define HID     128
#define BH      (BATCH * HID)

#define GRP_ROWS 64
#define NGRP     16
#define PSLC     8
#define JS       16
#define NCOLS    64
#define NCTA     (NGRP * PSLC)
#define NTHR     512

#define KTOT     448
#define KP_TOT   224
#define NKT      28
#define AST      164
#define BST      228
#define GST      68

// SMEM layout (u32 units): 3 A planes + B-hi + G0 + G1 + bias
#define S_A0     0
#define S_A1     (GRP_ROWS * AST)
#define S_A2     (2 * GRP_ROWS * AST)
#define S_BHI    (3 * GRP_ROWS * AST)
#define S_G0     (S_BHI + NCOLS * BST)          // 46080
#define S_G1     (S_G0 + GRP_ROWS * GST)        // 50432
#define S_BIAS   (S_G1 + GRP_ROWS * GST)        // 54784
#define SMEM_U32 (S_BIAS + 2 * NCOLS)           // 54912
#define SMEM_BYTES (SMEM_U32 * 4)               // 219648

// ---------------------------------------------------------------------------
// Global scratch
// ---------------------------------------------------------------------------
__device__ float    g_Wfull[4 * HID * KTOT];
__device__ unsigned g_BwHi[PSLC][NCOLS * BST];
__device__ uint4    g_Bfrag[2][PSLC][4][NKT][32];
__device__ float    g_bias[PSLC][2][NCOLS];
__device__ uint2    g_hbuf[2][2][NGRP][GRP_ROWS][HID];  // [parity][layer]
__device__ int      g_ctr[NGRP];

// ---------------------------------------------------------------------------
// helpers
// ---------------------------------------------------------------------------
__device__ __forceinline__ unsigned pack_bf(float e0, float e1) {
    unsigned lo = (unsigned)__bfloat16_as_ushort(__float2bfloat16_rn(e0));
    unsigned hi = (unsigned)__bfloat16_as_ushort(__float2bfloat16_rn(e1));
    return (hi << 16) | lo;
}
__device__ __forceinline__ void split3(float v, float& s0, float& s1, float& s2) {
    __nv_bfloat16 q0 = __float2bfloat16_rn(v);
    s0 = __bfloat162float(q0);
    float r = v - s0;
    __nv_bfloat16 q1 = __float2bfloat16_rn(r);
    s1 = __bfloat162float(q1);
    s2 = r - s1;
}
__device__ __forceinline__ float fsig(float x) {
    return __fdividef(1.f, 1.f + __expf(-x));
}
__device__ __forceinline__ float ftanh(float x) {
    return __fdividef(2.f, 1.f + __expf(-2.f * x)) - 1.f;
}
__device__ __forceinline__ void mma16816(float* c,
    unsigned a0, unsigned a1, unsigned a2, unsigned a3,
    unsigned b0, unsigned b1)
{
    asm volatile(
        "mma.sync.aligned.m16n8k16.row.col.f32.bf16.bf16.f32 "
        "{%0,%1,%2,%3}, {%4,%5,%6,%7}, {%8,%9}, {%0,%1,%2,%3};"
        : "+f"(c[0]), "+f"(c[1]), "+f"(c[2]), "+f"(c[3])
        : "r"(a0), "r"(a1), "r"(a2), "r"(a3), "r"(b0), "r"(b1));
}

// 6-term product set for one 16-wide k tile, both ntiles of one layer.
__device__ __forceinline__ void tile6(float* acc0, float* acc1,
    const unsigned* Af, const unsigned* __restrict__ sBhi,
    const uint4* __restrict__ fpm, const uint4* __restrict__ fpl,
    int bkt, int fg, int fq, int wn)
{
    int kb = 8 * bkt + fq;
    uint4 bm = fpm[bkt * 32];
    uint4 bl = fpl[bkt * 32];
    int nb0 = (16 * wn + fg) * BST + kb;
    {
        unsigned bh0 = sBhi[nb0], bh1 = sBhi[nb0 + 4];
        mma16816(acc0, Af[0], Af[1], Af[2],  Af[3],  bh0,  bh1);
        mma16816(acc0, Af[4], Af[5], Af[6],  Af[7],  bh0,  bh1);
        mma16816(acc0, Af[8], Af[9], Af[10], Af[11], bh0,  bh1);
        mma16816(acc0, Af[0], Af[1], Af[2],  Af[3],  bm.x, bm.y);
        mma16816(acc0, Af[4], Af[5], Af[6],  Af[7],  bm.x, bm.y);
        mma16816(acc0, Af[0], Af[1], Af[2],  Af[3],  bl.x, bl.y);
    }
    {
        int nb1 = nb0 + 8 * BST;
        unsigned bh0 = sBhi[nb1], bh1 = sBhi[nb1 + 4];
        mma16816(acc1, Af[0], Af[1], Af[2],  Af[3],  bh0,  bh1);
        mma16816(acc1, Af[4], Af[5], Af[6],  Af[7],  bh0,  bh1);
        mma16816(acc1, Af[8], Af[9], Af[10], Af[11], bh0,  bh1);
        mma16816(acc1, Af[0], Af[1], Af[2],  Af[3],  bm.z, bm.w);
        mma16816(acc1, Af[4], Af[5], Af[6],  Af[7],  bm.z, bm.w);
        mma16816(acc1, Af[0], Af[1], Af[2],  Af[3],  bl.z, bl.w);
    }
}

// ---------------------------------------------------------------------------
// prep1: full-precision fused weights + biases + barrier reset
// ---------------------------------------------------------------------------
__global__ void prep1_kernel(
    const float* __restrict__ pre_w,  const float* __restrict__ pre_b,
    const float* __restrict__ w_ih0,  const float* __restrict__ w_hh0,
    const float* __restrict__ b_ih0,  const float* __restrict__ b_hh0,
    const float* __restrict__ w_ih1,  const float* __restrict__ w_hh1,
    const float* __restrict__ b_ih1,  const float* __restrict__ b_hh1)
{
    int idx = blockIdx.x * blockDim.x + threadIdx.x;
    int stride = gridDim.x * blockDim.x;

    if (idx < NGRP) g_ctr[idx] = 0;

    for (int e = idx; e < 4 * HID * KTOT; e += stride) {
        int n = e / KTOT;
        int k = e % KTOT;
        float v;
        if (k < 64) {
            float s = 0.f;
            #pragma unroll 8
            for (int h = 0; h < HID; h++)
                s += w_ih0[n * HID + h] * pre_w[h * SEG + k];
            v = s;
        } else if (k < 192) {
            v = w_hh0[n * HID + (k - 64)];
        } else if (k < 320) {
            v = w_ih1[n * HID + (k - 192)];
        } else {
            v = w_hh1[n * HID + (k - 320)];
        }
        g_Wfull[e] = v;
    }

    for (int e = idx; e < PSLC * NCOLS; e += stride) {
        int js   = e / NCOLS;
        int ncol = e % NCOLS;
        int n    = (ncol & 3) * HID + js * JS + (ncol >> 2);
        float s = 0.f;
        for (int h = 0; h < HID; h++)
            s += w_ih0[n * HID + h] * pre_b[h];
        g_bias[js][0][ncol] = s + b_ih0[n] + b_hh0[n];
        g_bias[js][1][ncol] = b_ih1[n] + b_hh1[n];
    }
}

// ---------------------------------------------------------------------------
// prep2: hi plane (SMEM layout) + mid/lo fragment-major planes
// ---------------------------------------------------------------------------
__device__ __forceinline__ float wterm(int n, int k, int pl) {
    float v = g_Wfull[n * KTOT + k];
    float s0, s1, s2;
    split3(v, s0, s1, s2);
    return (pl == 0) ? s1 : s2;
}

__global__ void prep2_kernel()
{
    int idx = blockIdx.x * blockDim.x + threadIdx.x;
    int stride = gridDim.x * blockDim.x;

    for (int e = idx; e < PSLC * NCOLS * KP_TOT; e += stride) {
        int js   = e / (NCOLS * KP_TOT);
        int rem  = e % (NCOLS * KP_TOT);
        int ncol = rem / KP_TOT;
        int kp   = rem % KP_TOT;
        int n    = (ncol & 3) * HID + js * JS + (ncol >> 2);
        float v0 = g_Wfull[n * KTOT + 2 * kp];
        float v1 = g_Wfull[n * KTOT + 2 * kp + 1];
        float a, b, c, h0, h1;
        split3(v0, h0, a, b);
        split3(v1, h1, a, c);
        g_BwHi[js][ncol * BST + kp] = pack_bf(h0, h1);
    }

    for (int e = idx; e < 2 * PSLC * 4 * NKT * 32; e += stride) {
        int lane = e & 31;
        int t1   = e >> 5;
        int kt   = t1 % NKT;  t1 /= NKT;
        int wn   = t1 % 4;    t1 /= 4;
        int js   = t1 % PSLC;
        int pl   = t1 / PSLC;
        int fg   = lane >> 2;
        int fq   = lane & 3;
        int kp0  = 8 * kt + fq;
        int kp1  = kp0 + 4;
        int c0   = 16 * wn + fg;
        int c1   = c0 + 8;
        int n0   = (c0 & 3) * HID + js * JS + (c0 >> 2);
        int n1   = (c1 & 3) * HID + js * JS + (c1 >> 2);
        uint4 u;
        u.x = pack_bf(wterm(n0, 2 * kp0, pl), wterm(n0, 2 * kp0 + 1, pl));
        u.y = pack_bf(wterm(n0, 2 * kp1, pl), wterm(n0, 2 * kp1 + 1, pl));
        u.z = pack_bf(wterm(n1, 2 * kp0, pl), wterm(n1, 2 * kp0 + 1, pl));
        u.w = pack_bf(wterm(n1, 2 * kp1, pl), wterm(n1, 2 * kp1 + 1, pl));
        g_Bfrag[pl][js][wn][kt][lane] = u;
    }
}

// ---------------------------------------------------------------------------
// Persistent pipelined tensor-core LSTM (one barrier per step)
// ---------------------------------------------------------------------------
__global__ __launch_bounds__(NTHR, 1) void lstm_kernel(
    const float* __restrict__ x_in,
    const float* __restrict__ h0in,
    const float* __restrict__ c0in,
    const float* __restrict__ post_w,
    const float* __restrict__ post_b,
    float* __restrict__ out)
{
    extern __shared__ unsigned smem_u[];
    unsigned* sA0  = smem_u + S_A0;
    unsigned* sA1  = smem_u + S_A1;
    unsigned* sA2  = smem_u + S_A2;
    unsigned* sBhi = smem_u + S_BHI;
    float*    sG0  = (float*)(smem_u + S_G0);
    float*    sG1  = (float*)(smem_u + S_G1);
    float*    sBias= (float*)(smem_u + S_BIAS);

    const int tid  = threadIdx.x;
    const int grp  = blockIdx.x >> 3;
    const int js   = blockIdx.x & 7;
    const int wid  = tid >> 5;
    const int lane = tid & 31;
    const int wm   = wid & 3;
    const int wn   = wid >> 2;
    const int mr   = 16 * wm;
    const int fg   = lane >> 2;
    const int fq   = lane & 3;
    const int brow0 = grp * GRP_ROWS;

    for (int i = tid; i < NCOLS * BST; i += NTHR)
        sBhi[i] = g_BwHi[js][i];
    if (tid < 2 * NCOLS)
        sBias[tid] = g_bias[js][tid >> 6][tid & 63];

    // initial h0 -> A kpairs 32..95 (full 128 j, direct from input)
    for (int e = tid; e < 4096; e += NTHR) {
        int r = e >> 6, m = e & 63;
        const float2 v = *(const float2*)&h0in[0 * BH + (brow0 + r) * HID + 2 * m];
        float x0, x1, x2, y0, y1, y2;
        split3(v.x, x0, x1, x2);
        split3(v.y, y0, y1, y2);
        sA0[r * AST + 32 + m] = pack_bf(x0, y0);
        sA1[r * AST + 32 + m] = pack_bf(x1, y1);
        sA2[r * AST + 32 + m] = pack_bf(x2, y2);
    }
    // publish own slice of initial h1 into hbuf parity 0 (gathered at t=0)
    {
        for (int e = tid; e < GRP_ROWS * JS; e += NTHR) {
            int r = e / JS, jj = e % JS;
            float v = h0in[1 * BH + (brow0 + r) * HID + js * JS + jj];
            float s0, s1, s2;
            split3(v, s0, s1, s2);
            uint2 pk;
            pk.x = ((unsigned)__bfloat16_as_ushort(__float2bfloat16_rn(s0)) << 16)
                 | (unsigned)__bfloat16_as_ushort(__float2bfloat16_rn(s1));
            pk.y = (unsigned)__bfloat16_as_ushort(__float2bfloat16_rn(s2));
            g_hbuf[0][1][grp][r][js * JS + jj] = pk;
        }
    }

    // per-thread cell state
    float c0v[2], c1v[2], h0n[2], h1n[2];
    #pragma unroll
    for (int u = 0; u < 2; u++) {
        int p = tid + NTHR * u;
        int jj = p >> 6, r = p & 63;
        int j = js * JS + jj;
        int b = brow0 + r;
        c0v[u] = c0in[0 * BH + b * HID + j];
        c1v[u] = c0in[1 * BH + b * HID + j];
        h0n[u] = h0in[0 * BH + b * HID + j];
        h1n[u] = h0in[1 * BH + b * HID + j];
    }

    // stage x_0
    for (int e = tid; e < 2048; e += NTHR) {
        int r = e >> 5, kp = e & 31;
        const float2 xv = *(const float2*)&x_in[((long)(brow0 + r)) * SEG + 2 * kp];
        float x0, x1, x2, y0, y1, y2;
        split3(xv.x, x0, x1, x2);
        split3(xv.y, y0, y1, y2);
        sA0[r * AST + kp] = pack_bf(x0, y0);
        sA1[r * AST + kp] = pack_bf(x1, y1);
        sA2[r * AST + kp] = pack_bf(x2, y2);
    }
    __syncthreads();

    const uint4* fpm = &g_Bfrag[0][js][wn][0][lane];
    const uint4* fpl = &g_Bfrag[1][js][wn][0][lane];

    int phase = 0;

    // =================== prologue: layer 0, step 0 ===================
    {
        float a0[4] = {0, 0, 0, 0}, a1[4] = {0, 0, 0, 0};
        #pragma unroll 2
        for (int kt = 0; kt < 12; kt++) {
            int ra = (mr + fg) * AST + 8 * kt + fq;
            int rb = ra + 8 * AST;
            unsigned Af[12] = {
                sA0[ra], sA0[rb], sA0[ra + 4], sA0[rb + 4],
                sA1[ra], sA1[rb], sA1[ra + 4], sA1[rb + 4],
                sA2[ra], sA2[rb], sA2[ra + 4], sA2[rb + 4] };
            tile6(a0, a1, Af, sBhi, fpm, fpl, kt, fg, fq, wn);
        }
        int nb0 = 16 * wn, nb1 = 16 * wn + 8;
        *(float2*)&sG0[(mr + fg) * GST + nb0 + 2 * fq]     = make_float2(a0[0], a0[1]);
        *(float2*)&sG0[(mr + fg + 8) * GST + nb0 + 2 * fq] = make_float2(a0[2], a0[3]);
        *(float2*)&sG0[(mr + fg) * GST + nb1 + 2 * fq]     = make_float2(a1[0], a1[1]);
        *(float2*)&sG0[(mr + fg + 8) * GST + nb1 + 2 * fq] = make_float2(a1[2], a1[3]);
    }
    __syncthreads();
    #pragma unroll
    for (int u = 0; u < 2; u++) {
        int p = tid + NTHR * u;
        int jj = p >> 6, r = p & 63;
        float4 gv = *(const float4*)&sG0[r * GST + 4 * jj];
        float4 bb = *(const float4*)&sBias[4 * jj];
        float ig  = fsig(gv.x + bb.x);
        float fgt = fsig(gv.y + bb.y);
        float gg  = ftanh(gv.z + bb.z);
        float og  = fsig(gv.w + bb.w);
        c0v[u] = fgt * c0v[u] + ig * gg;
        h0n[u] = og * ftanh(c0v[u]);
        float s0, s1, s2;
        split3(h0n[u], s0, s1, s2);
        uint2 pk;
        pk.x = ((unsigned)__bfloat16_as_ushort(__float2bfloat16_rn(s0)) << 16)
             | (unsigned)__bfloat16_as_ushort(__float2bfloat16_rn(s1));
        pk.y = (unsigned)__bfloat16_as_ushort(__float2bfloat16_rn(s2));
        g_hbuf[0][0][grp][r][js * JS + jj] = pk;   // h0_0 -> parity 0
    }
    __threadfence();
    __syncthreads();
    phase++;
    if (tid == 0) {
        atomicAdd(&g_ctr[grp], 1);
        while (*(volatile int*)&g_ctr[grp] < phase * PSLC) __nanosleep(64);
    }
    __syncthreads();

    // =================== main loop ===================
    for (int t = 0; t < T_STEPS - 1; t++) {
        const int gpar = t & 1;
        const int ppar = (t + 1) & 1;

        // stage x_{t+1}
        for (int e = tid; e < 2048; e += NTHR) {
            int r = e >> 5, kp = e & 31;
            const float2 xv = *(const float2*)&x_in[((long)(t + 1) * BATCH + brow0 + r) * SEG + 2 * kp];
            float x0, x1, x2, y0, y1, y2;
            split3(xv.x, x0, x1, x2);
            split3(xv.y, y0, y1, y2);
            sA0[r * AST + kp] = pack_bf(x0, y0);
            sA1[r * AST + kp] = pack_bf(x1, y1);
            sA2[r * AST + kp] = pack_bf(x2, y2);
        }
        // gather h0_t (kp 32..95) and h1_{t-1} (kp 96..159) from parity gpar
        for (int e = tid; e < 4096; e += NTHR) {
            int r = e >> 6, m = e & 63;
            uint4 q0 = __ldcg((const uint4*)&g_hbuf[gpar][0][grp][r][2 * m]);
            sA0[r * AST + 32 + m] = (q0.z & 0xffff0000u) | (q0.x >> 16);
            sA1[r * AST + 32 + m] = ((q0.z & 0xffffu) << 16) | (q0.x & 0xffffu);
            sA2[r * AST + 32 + m] = ((q0.w & 0xffffu) << 16) | (q0.y & 0xffffu);
            uint4 q1 = __ldcg((const uint4*)&g_hbuf[gpar][1][grp][r][2 * m]);
            sA0[r * AST + 96 + m] = (q1.z & 0xffff0000u) | (q1.x >> 16);
            sA1[r * AST + 96 + m] = ((q1.z & 0xffffu) << 16) | (q1.x & 0xffffu);
            sA2[r * AST + 96 + m] = ((q1.w & 0xffffu) << 16) | (q1.y & 0xffffu);
        }
        __syncthreads();

        // combined sweep: layer0(t+1) into aL0, layer1(t) into aL1
        {
            float aL0a[4] = {0,0,0,0}, aL0b[4] = {0,0,0,0};
            float aL1a[4] = {0,0,0,0}, aL1b[4] = {0,0,0,0};
            #pragma unroll 2
            for (int kt = 0; kt < 4; kt++) {        // x part: L0 only
                int ra = (mr + fg) * AST + 8 * kt + fq;
                int rb = ra + 8 * AST;
                unsigned Af[12] = {
                    sA0[ra], sA0[rb], sA0[ra + 4], sA0[rb + 4],
                    sA1[ra], sA1[rb], sA1[ra + 4], sA1[rb + 4],
                    sA2[ra], sA2[rb], sA2[ra + 4], sA2[rb + 4] };
                tile6(aL0a, aL0b, Af, sBhi, fpm, fpl, kt, fg, fq, wn);
            }
            #pragma unroll 2
            for (int kt = 4; kt < 12; kt++) {       // h0 part: both layers
                int ra = (mr + fg) * AST + 8 * kt + fq;
                int rb = ra + 8 * AST;
                unsigned Af[12] = {
                    sA0[ra], sA0[rb], sA0[ra + 4], sA0[rb + 4],
                    sA1[ra], sA1[rb], sA1[ra + 4], sA1[rb + 4],
                    sA2[ra], sA2[rb], sA2[ra + 4], sA2[rb + 4] };
                tile6(aL0a, aL0b, Af, sBhi, fpm, fpl, kt, fg, fq, wn);
                tile6(aL1a, aL1b, Af, sBhi, fpm, fpl, kt + 8, fg, fq, wn);
            }
            #pragma unroll 2
            for (int kt = 12; kt < 20; kt++) {      // h1 part: L1 only
                int ra = (mr + fg) * AST + 8 * kt + fq;
                int rb = ra + 8 * AST;
                unsigned Af[12] = {
                    sA0[ra], sA0[rb], sA0[ra + 4], sA0[rb + 4],
                    sA1[ra], sA1[rb], sA1[ra + 4], sA1[rb + 4],
                    sA2[ra], sA2[rb], sA2[ra + 4], sA2[rb + 4] };
                tile6(aL1a, aL1b, Af, sBhi, fpm, fpl, kt + 8, fg, fq, wn);
            }
            int nb0 = 16 * wn, nb1 = 16 * wn + 8;
            *(float2*)&sG0[(mr + fg) * GST + nb0 + 2 * fq]     = make_float2(aL0a[0], aL0a[1]);
            *(float2*)&sG0[(mr + fg + 8) * GST + nb0 + 2 * fq] = make_float2(aL0a[2], aL0a[3]);
            *(float2*)&sG0[(mr + fg) * GST + nb1 + 2 * fq]     = make_float2(aL0b[0], aL0b[1]);
            *(float2*)&sG0[(mr + fg + 8) * GST + nb1 + 2 * fq] = make_float2(aL0b[2], aL0b[3]);
            *(float2*)&sG1[(mr + fg) * GST + nb0 + 2 * fq]     = make_float2(aL1a[0], aL1a[1]);
            *(float2*)&sG1[(mr + fg + 8) * GST + nb0 + 2 * fq] = make_float2(aL1a[2], aL1a[3]);
            *(float2*)&sG1[(mr + fg) * GST + nb1 + 2 * fq]     = make_float2(aL1b[0], aL1b[1]);
            *(float2*)&sG1[(mr + fg + 8) * GST + nb1 + 2 * fq] = make_float2(aL1b[2], aL1b[3]);
        }
        __syncthreads();

        // state updates: layer1(t) and layer0(t+1); publish to parity ppar
        #pragma unroll
        for (int u = 0; u < 2; u++) {
            int p = tid + NTHR * u;
            int jj = p >> 6, r = p & 63;
            // layer 1
            {
                float4 gv = *(const float4*)&sG1[r * GST + 4 * jj];
                float4 bb = *(const float4*)&sBias[64 + 4 * jj];
                float ig  = fsig(gv.x + bb.x);
                float fgt = fsig(gv.y + bb.y);
                float gg  = ftanh(gv.z + bb.z);
                float og  = fsig(gv.w + bb.w);
                c1v[u] = fgt * c1v[u] + ig * gg;
                h1n[u] = og * ftanh(c1v[u]);
                float s0, s1, s2;
                split3(h1n[u], s0, s1, s2);
                uint2 pk;
                pk.x = ((unsigned)__bfloat16_as_ushort(__float2bfloat16_rn(s0)) << 16)
                     | (unsigned)__bfloat16_as_ushort(__float2bfloat16_rn(s1));
                pk.y = (unsigned)__bfloat16_as_ushort(__float2bfloat16_rn(s2));
                g_hbuf[ppar][1][grp][r][js * JS + jj] = pk;
            }
            // layer 0 (step t+1)
            {
                float4 gv = *(const float4*)&sG0[r * GST + 4 * jj];
                float4 bb = *(const float4*)&sBias[4 * jj];
                float ig  = fsig(gv.x + bb.x);
                float fgt = fsig(gv.y + bb.y);
                float gg  = ftanh(gv.z + bb.z);
                float og  = fsig(gv.w + bb.w);
                c0v[u] = fgt * c0v[u] + ig * gg;
                h0n[u] = og * ftanh(c0v[u]);
                float s0, s1, s2;
                split3(h0n[u], s0, s1, s2);
                uint2 pk;
                pk.x = ((unsigned)__bfloat16_as_ushort(__float2bfloat16_rn(s0)) << 16)
                     | (unsigned)__bfloat16_as_ushort(__float2bfloat16_rn(s1));
                pk.y = (unsigned)__bfloat16_as_ushort(__float2bfloat16_rn(s2));
                g_hbuf[ppar][0][grp][r][js * JS + jj] = pk;
            }
        }
        __threadfence();
        __syncthreads();
        phase++;
        if (tid == 0) {
            atomicAdd(&g_ctr[grp], 1);
            while (*(volatile int*)&g_ctr[grp] < phase * PSLC) __nanosleep(64);
        }
        __syncthreads();
    }

    // =================== epilogue: layer 1, step 255 ===================
    {
        const int gpar = (T_STEPS - 1) & 1;   // = 1
        for (int e = tid; e < 4096; e += NTHR) {
            int r = e >> 6, m = e & 63;
            uint4 q0 = __ldcg((const uint4*)&g_hbuf[gpar][0][grp][r][2 * m]);
            sA0[r * AST + 32 + m] = (q0.z & 0xffff0000u) | (q0.x >> 16);
            sA1[r * AST + 32 + m] = ((q0.z & 0xffffu) << 16) | (q0.x & 0xffffu);
            sA2[r * AST + 32 + m] = ((q0.w & 0xffffu) << 16) | (q0.y & 0xffffu);
            uint4 q1 = __ldcg((const uint4*)&g_hbuf[gpar][1][grp][r][2 * m]);
            sA0[r * AST + 96 + m] = (q1.z & 0xffff0000u) | (q1.x >> 16);
            sA1[r * AST + 96 + m] = ((q1.z & 0xffffu) << 16) | (q1.x & 0xffffu);
            sA2[r * AST + 96 + m] = ((q1.w & 0xffffu) << 16) | (q1.y & 0xffffu);
        }
        __syncthreads();
        float a0[4] = {0, 0, 0, 0}, a1[4] = {0, 0, 0, 0};
        #pragma unroll 2
        for (int kt = 4; kt < 20; kt++) {
            int ra = (mr + fg) * AST + 8 * kt + fq;
            int rb = ra + 8 * AST;
            unsigned Af[12] = {
                sA0[ra], sA0[rb], sA0[ra + 4], sA0[rb + 4],
                sA1[ra], sA1[rb], sA1[ra + 4], sA1[rb + 4],
                sA2[ra], sA2[rb], sA2[ra + 4], sA2[rb + 4] };
            tile6(a0, a1, Af, sBhi, fpm, fpl, kt + 8, fg, fq, wn);
        }
        int nb0 = 16 * wn, nb1 = 16 * wn + 8;
        *(float2*)&sG1[(mr + fg) * GST + nb0 + 2 * fq]     = make_float2(a0[0], a0[1]);
        *(float2*)&sG1[(mr + fg + 8) * GST + nb0 + 2 * fq] = make_float2(a0[2], a0[3]);
        *(float2*)&sG1[(mr + fg) * GST + nb1 + 2 * fq]     = make_float2(a1[0], a1[1]);
        *(float2*)&sG1[(mr + fg + 8) * GST + nb1 + 2 * fq] = make_float2(a1[2], a1[3]);
    }
    __syncthreads();
    #pragma unroll
    for (int u = 0; u < 2; u++) {
        int p = tid + NTHR * u;
        int jj = p >> 6, r = p & 63;
        float4 gv = *(const float4*)&sG1[r * GST + 4 * jj];
        float4 bb = *(const float4*)&sBias[64 + 4 * jj];
        float ig  = fsig(gv.x + bb.x);
        float fgt = fsig(gv.y + bb.y);
        float gg  = ftanh(gv.z + bb.z);
        float og  = fsig(gv.w + bb.w);
        c1v[u] = fgt * c1v[u] + ig * gg;
        h1n[u] = og * ftanh(c1v[u]);
        float s0, s1, s2;
        split3(h1n[u], s0, s1, s2);
        uint2 pk;
        pk.x = ((unsigned)__bfloat16_as_ushort(__float2bfloat16_rn(s0)) << 16)
             | (unsigned)__bfloat16_as_ushort(__float2bfloat16_rn(s1));
        pk.y = (unsigned)__bfloat16_as_ushort(__float2bfloat16_rn(s2));
        g_hbuf[0][1][grp][r][js * JS + jj] = pk;   // h1_255 for pred
    }
    __threadfence();
    __syncthreads();
    phase++;
    if (tid == 0) {
        atomicAdd(&g_ctr[grp], 1);
        while (*(volatile int*)&g_ctr[grp] < phase * PSLC) __nanosleep(64);
    }
    __syncthreads();

    // ---------------- outputs ----------------
    const int OH = BATCH;
    const int OC = BATCH + 2 * BH;
    #pragma unroll
    for (int u = 0; u < 2; u++) {
        int p = tid + NTHR * u;
        int jj = p >> 6, r = p & 63;
        int j = js * JS + jj;
        int b = brow0 + r;
        out[OH + 0 * BH + b * HID + j] = h0n[u];
        out[OH + 1 * BH + b * HID + j] = h1n[u];
        out[OC + 0 * BH + b * HID + j] = c0v[u];
        out[OC + 1 * BH + b * HID + j] = c1v[u];
    }

    if (js == 0 && tid < GRP_ROWS) {
        int r = tid;
        float s = 0.f;
        #pragma unroll 8
        for (int m = 0; m < HID; m++) {
            uint2 pk = __ldcg(&g_hbuf[0][1][grp][r][m]);
            float hv = __bfloat162float(__ushort_as_bfloat16((unsigned short)(pk.x >> 16)))
                     + __bfloat162float(__ushort_as_bfloat16((unsigned short)(pk.x & 0xffffu)))
                     + __bfloat162float(__ushort_as_bfloat16((unsigned short)(pk.y & 0xffffu)));
            s += fmaxf(hv, 0.f) * post_w[m];
        }
        out[brow0 + r] = s + post_b[0];
    }
}

extern "C" void kernel_launch(void* const* d_in, const int* in_sizes, int n_in,
                              void* d_out, int out_size)
{
    const float* x_in   = (const float*)d_in[0];
    const float* h0     = (const float*)d_in[1];
    const float* c0     = (const float*)d_in[2];
    const float* pre_w  = (const float*)d_in[3];
    const float* pre_b  = (const float*)d_in[4];
    const float* w_ih0  = (const float*)d_in[5];
    const float* w_hh0  = (const float*)d_in[6];
    const float* b_ih0  = (const float*)d_in[7];
    const float* b_hh0  = (const float*)d_in[8];
    const float* w_ih1  = (const float*)d_in[9];
    const float* w_hh1  = (const float*)d_in[10];
    const float* b_ih1  = (const float*)d_in[11];
    const float* b_hh1  = (const float*)d_in[12];
    const float* post_w = (const float*)d_in[13];
    const float* post_b = (const float*)d_in[14];
    float* out = (float*)d_out;

    static int attr_set = 0;
    if (!attr_set) {
        cudaFuncSetAttribute(lstm_kernel,
                             cudaFuncAttributeMaxDynamicSharedMemorySize,
                             SMEM_BYTES);
        attr_set = 1;
    }

    prep1_kernel<<<192, 256>>>(pre_w, pre_b, w_ih0, w_hh0, b_ih0, b_hh0,
                               w_ih1, w_hh1, b_ih1, b_hh1);
    prep2_kernel<<<192, 256>>>();
    lstm_kernel<<<NCTA, NTHR, SMEM_BYTES>>>(x_in, h0, c0, post_w, post_b, out);
}

// round 17
// speedup vs baseline: 1.9165x; 1.1754x over previous
#include <cuda_runtime.h>
#include <cuda_bf16.h>
#include <math.h>

// ---------------------------------------------------------------------------
// Problem constants
// ---------------------------------------------------------------------------
#define T_STEPS 256
#define BATCH   1024
#define SEG     64
#define HID     128
#define BH      (BATCH * HID)

#define GRP_ROWS 64
#define NGRP     16
#define PSLC     8
#define JS       16
#define NCOLS    64
#define NCTA     (NGRP * PSLC)
#define NTHR     512

#define KTOT     448
#define KP_TOT   224
#define NKT      28
#define AST      164
#define BST      228

// SMEM layout (u32 units): 3 A planes + B-hi + bias
#define S_A0     0
#define S_A1     (GRP_ROWS * AST)
#define S_A2     (2 * GRP_ROWS * AST)
#define S_BHI    (3 * GRP_ROWS * AST)            // 31488
#define S_BIAS   (S_BHI + NCOLS * BST)           // 46080
#define SMEM_U32 (S_BIAS + 2 * NCOLS)            // 46208
#define SMEM_BYTES (SMEM_U32 * 4)                // 184832

// ---------------------------------------------------------------------------
// Global scratch
// ---------------------------------------------------------------------------
__device__ float    g_Wfull[4 * HID * KTOT];
__device__ unsigned g_BwHi[PSLC][NCOLS * BST];
__device__ uint4    g_Bfrag[2][PSLC][4][NKT][32];
__device__ float    g_bias[PSLC][2][NCOLS];
__device__ uint2    g_hbuf[2][2][NGRP][GRP_ROWS][HID];  // [parity][layer]
__device__ int      g_ctr[NGRP];

// ---------------------------------------------------------------------------
// helpers
// ---------------------------------------------------------------------------
__device__ __forceinline__ unsigned pack_bf(float e0, float e1) {
    unsigned lo = (unsigned)__bfloat16_as_ushort(__float2bfloat16_rn(e0));
    unsigned hi = (unsigned)__bfloat16_as_ushort(__float2bfloat16_rn(e1));
    return (hi << 16) | lo;
}
__device__ __forceinline__ void split3(float v, float& s0, float& s1, float& s2) {
    __nv_bfloat16 q0 = __float2bfloat16_rn(v);
    s0 = __bfloat162float(q0);
    float r = v - s0;
    __nv_bfloat16 q1 = __float2bfloat16_rn(r);
    s1 = __bfloat162float(q1);
    s2 = r - s1;
}
__device__ __forceinline__ float fsig(float x) {
    return __fdividef(1.f, 1.f + __expf(-x));
}
__device__ __forceinline__ float ftanh(float x) {
    return __fdividef(2.f, 1.f + __expf(-2.f * x)) - 1.f;
}
__device__ __forceinline__ void mma16816(float* c,
    unsigned a0, unsigned a1, unsigned a2, unsigned a3,
    unsigned b0, unsigned b1)
{
    asm volatile(
        "mma.sync.aligned.m16n8k16.row.col.f32.bf16.bf16.f32 "
        "{%0,%1,%2,%3}, {%4,%5,%6,%7}, {%8,%9}, {%0,%1,%2,%3};"
        : "+f"(c[0]), "+f"(c[1]), "+f"(c[2]), "+f"(c[3])
        : "r"(a0), "r"(a1), "r"(a2), "r"(a3), "r"(b0), "r"(b1));
}

// 6-term product set for one 16-wide k tile, both ntiles of one layer.
__device__ __forceinline__ void tile6(float* acc0, float* acc1,
    const unsigned* Af, const unsigned* __restrict__ sBhi,
    const uint4* __restrict__ fpm, const uint4* __restrict__ fpl,
    int bkt, int fg, int fq, int wn)
{
    int kb = 8 * bkt + fq;
    uint4 bm = fpm[bkt * 32];
    uint4 bl = fpl[bkt * 32];
    int nb0 = (16 * wn + fg) * BST + kb;
    {
        unsigned bh0 = sBhi[nb0], bh1 = sBhi[nb0 + 4];
        mma16816(acc0, Af[0], Af[1], Af[2],  Af[3],  bh0,  bh1);
        mma16816(acc0, Af[4], Af[5], Af[6],  Af[7],  bh0,  bh1);
        mma16816(acc0, Af[8], Af[9], Af[10], Af[11], bh0,  bh1);
        mma16816(acc0, Af[0], Af[1], Af[2],  Af[3],  bm.x, bm.y);
        mma16816(acc0, Af[4], Af[5], Af[6],  Af[7],  bm.x, bm.y);
        mma16816(acc0, Af[0], Af[1], Af[2],  Af[3],  bl.x, bl.y);
    }
    {
        int nb1 = nb0 + 8 * BST;
        unsigned bh0 = sBhi[nb1], bh1 = sBhi[nb1 + 4];
        mma16816(acc1, Af[0], Af[1], Af[2],  Af[3],  bh0,  bh1);
        mma16816(acc1, Af[4], Af[5], Af[6],  Af[7],  bh0,  bh1);
        mma16816(acc1, Af[8], Af[9], Af[10], Af[11], bh0,  bh1);
        mma16816(acc1, Af[0], Af[1], Af[2],  Af[3],  bm.z, bm.w);
        mma16816(acc1, Af[4], Af[5], Af[6],  Af[7],  bm.z, bm.w);
        mma16816(acc1, Af[0], Af[1], Af[2],  Af[3],  bl.z, bl.w);
    }
}

// shuffle-based gate exchange + LSTM cell update + publish for ONE cell.
// acc: this thread's 4 fp32 accumulators for one ntile-half.
// odd = fq&1. Returns h; updates c in place; writes packed uint2 to dst.
__device__ __forceinline__ void cell_update(
    const float* acc, float4 bb, int odd, float& c, float& h, uint2* dst)
{
    float e0 = __shfl_xor_sync(0xffffffffu, acc[0], 1);
    float e1 = __shfl_xor_sync(0xffffffffu, acc[1], 1);
    float e2 = __shfl_xor_sync(0xffffffffu, acc[2], 1);
    float e3 = __shfl_xor_sync(0xffffffffu, acc[3], 1);
    float gi = odd ? e2     : acc[0];
    float gf = odd ? e3     : acc[1];
    float gg = odd ? acc[2] : e0;
    float go = odd ? acc[3] : e1;
    gi = fsig(gi + bb.x);
    gf = fsig(gf + bb.y);
    gg = ftanh(gg + bb.z);
    go = fsig(go + bb.w);
    c = gf * c + gi * gg;
    h = go * ftanh(c);
    float s0, s1, s2;
    split3(h, s0, s1, s2);
    uint2 pk;
    pk.x = ((unsigned)__bfloat16_as_ushort(__float2bfloat16_rn(s0)) << 16)
         | (unsigned)__bfloat16_as_ushort(__float2bfloat16_rn(s1));
    pk.y = (unsigned)__bfloat16_as_ushort(__float2bfloat16_rn(s2));
    *dst = pk;
}

// ---------------------------------------------------------------------------
// prep1: full-precision fused weights + biases + barrier reset
// ---------------------------------------------------------------------------
__global__ void prep1_kernel(
    const float* __restrict__ pre_w,  const float* __restrict__ pre_b,
    const float* __restrict__ w_ih0,  const float* __restrict__ w_hh0,
    const float* __restrict__ b_ih0,  const float* __restrict__ b_hh0,
    const float* __restrict__ w_ih1,  const float* __restrict__ w_hh1,
    const float* __restrict__ b_ih1,  const float* __restrict__ b_hh1)
{
    int idx = blockIdx.x * blockDim.x + threadIdx.x;
    int stride = gridDim.x * blockDim.x;

    if (idx < NGRP) g_ctr[idx] = 0;

    for (int e = idx; e < 4 * HID * KTOT; e += stride) {
        int n = e / KTOT;
        int k = e % KTOT;
        float v;
        if (k < 64) {
            float s = 0.f;
            #pragma unroll 8
            for (int h = 0; h < HID; h++)
                s += w_ih0[n * HID + h] * pre_w[h * SEG + k];
            v = s;
        } else if (k < 192) {
            v = w_hh0[n * HID + (k - 64)];
        } else if (k < 320) {
            v = w_ih1[n * HID + (k - 192)];
        } else {
            v = w_hh1[n * HID + (k - 320)];
        }
        g_Wfull[e] = v;
    }

    for (int e = idx; e < PSLC * NCOLS; e += stride) {
        int js   = e / NCOLS;
        int ncol = e % NCOLS;
        int n    = (ncol & 3) * HID + js * JS + (ncol >> 2);
        float s = 0.f;
        for (int h = 0; h < HID; h++)
            s += w_ih0[n * HID + h] * pre_b[h];
        g_bias[js][0][ncol] = s + b_ih0[n] + b_hh0[n];
        g_bias[js][1][ncol] = b_ih1[n] + b_hh1[n];
    }
}

// ---------------------------------------------------------------------------
// prep2: hi plane (SMEM layout) + mid/lo fragment-major planes
// ---------------------------------------------------------------------------
__device__ __forceinline__ float wterm(int n, int k, int pl) {
    float v = g_Wfull[n * KTOT + k];
    float s0, s1, s2;
    split3(v, s0, s1, s2);
    return (pl == 0) ? s1 : s2;
}

__global__ void prep2_kernel()
{
    int idx = blockIdx.x * blockDim.x + threadIdx.x;
    int stride = gridDim.x * blockDim.x;

    for (int e = idx; e < PSLC * NCOLS * KP_TOT; e += stride) {
        int js   = e / (NCOLS * KP_TOT);
        int rem  = e % (NCOLS * KP_TOT);
        int ncol = rem / KP_TOT;
        int kp   = rem % KP_TOT;
        int n    = (ncol & 3) * HID + js * JS + (ncol >> 2);
        float v0 = g_Wfull[n * KTOT + 2 * kp];
        float v1 = g_Wfull[n * KTOT + 2 * kp + 1];
        float a, b, c, h0, h1;
        split3(v0, h0, a, b);
        split3(v1, h1, a, c);
        g_BwHi[js][ncol * BST + kp] = pack_bf(h0, h1);
    }

    for (int e = idx; e < 2 * PSLC * 4 * NKT * 32; e += stride) {
        int lane = e & 31;
        int t1   = e >> 5;
        int kt   = t1 % NKT;  t1 /= NKT;
        int wn   = t1 % 4;    t1 /= 4;
        int js   = t1 % PSLC;
        int pl   = t1 / PSLC;
        int fg   = lane >> 2;
        int fq   = lane & 3;
        int kp0  = 8 * kt + fq;
        int kp1  = kp0 + 4;
        int c0   = 16 * wn + fg;
        int c1   = c0 + 8;
        int n0   = (c0 & 3) * HID + js * JS + (c0 >> 2);
        int n1   = (c1 & 3) * HID + js * JS + (c1 >> 2);
        uint4 u;
        u.x = pack_bf(wterm(n0, 2 * kp0, pl), wterm(n0, 2 * kp0 + 1, pl));
        u.y = pack_bf(wterm(n0, 2 * kp1, pl), wterm(n0, 2 * kp1 + 1, pl));
        u.z = pack_bf(wterm(n1, 2 * kp0, pl), wterm(n1, 2 * kp0 + 1, pl));
        u.w = pack_bf(wterm(n1, 2 * kp1, pl), wterm(n1, 2 * kp1 + 1, pl));
        g_Bfrag[pl][js][wn][kt][lane] = u;
    }
}

// ---------------------------------------------------------------------------
// Persistent pipelined tensor-core LSTM (shuffle update, overlapped barrier)
// ---------------------------------------------------------------------------
__global__ __launch_bounds__(NTHR, 1) void lstm_kernel(
    const float* __restrict__ x_in,
    const float* __restrict__ h0in,
    const float* __restrict__ c0in,
    const float* __restrict__ post_w,
    const float* __restrict__ post_b,
    float* __restrict__ out)
{
    extern __shared__ unsigned smem_u[];
    unsigned* sA0  = smem_u + S_A0;
    unsigned* sA1  = smem_u + S_A1;
    unsigned* sA2  = smem_u + S_A2;
    unsigned* sBhi = smem_u + S_BHI;
    float*    sBias= (float*)(smem_u + S_BIAS);

    const int tid  = threadIdx.x;
    const int grp  = blockIdx.x >> 3;
    const int js   = blockIdx.x & 7;
    const int wid  = tid >> 5;
    const int lane = tid & 31;
    const int wm   = wid & 3;
    const int wn   = wid >> 2;
    const int mr   = 16 * wm;
    const int fg   = lane >> 2;
    const int fq   = lane & 3;
    const int odd  = fq & 1;
    const int brow0 = grp * GRP_ROWS;

    // this thread's 2 cells: row ra, jj_a (ntile0), jj_b (ntile1)
    const int ra   = mr + fg + 8 * odd;       // local row 0..63
    const int jja  = 4 * wn + (fq >> 1);      // 0..15
    const int jjb  = jja + 2;
    const int ja   = js * JS + jja;           // global j
    const int jb   = js * JS + jjb;

    for (int i = tid; i < NCOLS * BST; i += NTHR)
        sBhi[i] = g_BwHi[js][i];
    if (tid < 2 * NCOLS)
        sBias[tid] = g_bias[js][tid >> 6][tid & 63];

    // initial h0 -> A kpairs 32..95
    for (int e = tid; e < 4096; e += NTHR) {
        int r = e >> 6, m = e & 63;
        const float2 v = *(const float2*)&h0in[0 * BH + (brow0 + r) * HID + 2 * m];
        float x0, x1, x2, y0, y1, y2;
        split3(v.x, x0, x1, x2);
        split3(v.y, y0, y1, y2);
        sA0[r * AST + 32 + m] = pack_bf(x0, y0);
        sA1[r * AST + 32 + m] = pack_bf(x1, y1);
        sA2[r * AST + 32 + m] = pack_bf(x2, y2);
    }
    // publish own slice of initial h1 into hbuf parity 0
    for (int e = tid; e < GRP_ROWS * JS; e += NTHR) {
        int r = e / JS, jj = e % JS;
        float v = h0in[1 * BH + (brow0 + r) * HID + js * JS + jj];
        float s0, s1, s2;
        split3(v, s0, s1, s2);
        uint2 pk;
        pk.x = ((unsigned)__bfloat16_as_ushort(__float2bfloat16_rn(s0)) << 16)
             | (unsigned)__bfloat16_as_ushort(__float2bfloat16_rn(s1));
        pk.y = (unsigned)__bfloat16_as_ushort(__float2bfloat16_rn(s2));
        g_hbuf[0][1][grp][r][js * JS + jj] = pk;
    }

    // cell state (fragment-derived mapping)
    float c0a, c0b, c1a, c1b, h0a, h0b, h1a, h1b;
    {
        int b = brow0 + ra;
        c0a = c0in[0 * BH + b * HID + ja];
        c0b = c0in[0 * BH + b * HID + jb];
        c1a = c0in[1 * BH + b * HID + ja];
        c1b = c0in[1 * BH + b * HID + jb];
        h0a = h0in[0 * BH + b * HID + ja];
        h0b = h0in[0 * BH + b * HID + jb];
        h1a = h0in[1 * BH + b * HID + ja];
        h1b = h0in[1 * BH + b * HID + jb];
    }

    // stage x_0
    for (int e = tid; e < 2048; e += NTHR) {
        int r = e >> 5, kp = e & 31;
        const float2 xv = *(const float2*)&x_in[((long)(brow0 + r)) * SEG + 2 * kp];
        float x0, x1, x2, y0, y1, y2;
        split3(xv.x, x0, x1, x2);
        split3(xv.y, y0, y1, y2);
        sA0[r * AST + kp] = pack_bf(x0, y0);
        sA1[r * AST + kp] = pack_bf(x1, y1);
        sA2[r * AST + kp] = pack_bf(x2, y2);
    }
    __syncthreads();

    const uint4* fpm = &g_Bfrag[0][js][wn][0][lane];
    const uint4* fpl = &g_Bfrag[1][js][wn][0][lane];

    // biases (register resident)
    float4 b0a, b0b, b1a, b1b;
    b0a = *(const float4*)&sBias[4 * jja];
    b0b = *(const float4*)&sBias[4 * jjb];
    b1a = *(const float4*)&sBias[64 + 4 * jja];
    b1b = *(const float4*)&sBias[64 + 4 * jjb];

    int phase = 0;

    // =================== prologue: layer 0, step 0 ===================
    {
        float a0[4] = {0, 0, 0, 0}, a1[4] = {0, 0, 0, 0};
        #pragma unroll 2
        for (int kt = 0; kt < 12; kt++) {
            int rA = (mr + fg) * AST + 8 * kt + fq;
            int rB = rA + 8 * AST;
            unsigned Af[12] = {
                sA0[rA], sA0[rB], sA0[rA + 4], sA0[rB + 4],
                sA1[rA], sA1[rB], sA1[rA + 4], sA1[rB + 4],
                sA2[rA], sA2[rB], sA2[rA + 4], sA2[rB + 4] };
            tile6(a0, a1, Af, sBhi, fpm, fpl, kt, fg, fq, wn);
        }
        cell_update(a0, b0a, odd, c0a, h0a, &g_hbuf[0][0][grp][ra][ja]);
        cell_update(a1, b0b, odd, c0b, h0b, &g_hbuf[0][0][grp][ra][jb]);
    }
    __threadfence();
    __syncthreads();
    phase++;
    if (tid == 0) atomicAdd(&g_ctr[grp], 1);
    // stage x_1 (overlaps barrier skew)
    for (int e = tid; e < 2048; e += NTHR) {
        int r = e >> 5, kp = e & 31;
        const float2 xv = *(const float2*)&x_in[((long)BATCH + brow0 + r) * SEG + 2 * kp];
        float x0, x1, x2, y0, y1, y2;
        split3(xv.x, x0, x1, x2);
        split3(xv.y, y0, y1, y2);
        sA0[r * AST + kp] = pack_bf(x0, y0);
        sA1[r * AST + kp] = pack_bf(x1, y1);
        sA2[r * AST + kp] = pack_bf(x2, y2);
    }
    if (tid == 0) {
        while (*(volatile int*)&g_ctr[grp] < phase * PSLC) __nanosleep(64);
    }
    __syncthreads();

    // =================== main loop ===================
    for (int t = 0; t < T_STEPS - 1; t++) {
        const int gpar = t & 1;
        const int ppar = (t + 1) & 1;

        // gather h0_t (kp 32..95) and h1_{t-1} (kp 96..159) from parity gpar
        for (int e = tid; e < 4096; e += NTHR) {
            int r = e >> 6, m = e & 63;
            uint4 q0 = __ldcg((const uint4*)&g_hbuf[gpar][0][grp][r][2 * m]);
            sA0[r * AST + 32 + m] = (q0.z & 0xffff0000u) | (q0.x >> 16);
            sA1[r * AST + 32 + m] = ((q0.z & 0xffffu) << 16) | (q0.x & 0xffffu);
            sA2[r * AST + 32 + m] = ((q0.w & 0xffffu) << 16) | (q0.y & 0xffffu);
            uint4 q1 = __ldcg((const uint4*)&g_hbuf[gpar][1][grp][r][2 * m]);
            sA0[r * AST + 96 + m] = (q1.z & 0xffff0000u) | (q1.x >> 16);
            sA1[r * AST + 96 + m] = ((q1.z & 0xffffu) << 16) | (q1.x & 0xffffu);
            sA2[r * AST + 96 + m] = ((q1.w & 0xffffu) << 16) | (q1.y & 0xffffu);
        }
        __syncthreads();

        // combined sweep: layer0(t+1), layer1(t)
        float aL0a[4] = {0,0,0,0}, aL0b[4] = {0,0,0,0};
        float aL1a[4] = {0,0,0,0}, aL1b[4] = {0,0,0,0};
        #pragma unroll 2
        for (int kt = 0; kt < 4; kt++) {
            int rA = (mr + fg) * AST + 8 * kt + fq;
            int rB = rA + 8 * AST;
            unsigned Af[12] = {
                sA0[rA], sA0[rB], sA0[rA + 4], sA0[rB + 4],
                sA1[rA], sA1[rB], sA1[rA + 4], sA1[rB + 4],
                sA2[rA], sA2[rB], sA2[rA + 4], sA2[rB + 4] };
            tile6(aL0a, aL0b, Af, sBhi, fpm, fpl, kt, fg, fq, wn);
        }
        #pragma unroll 2
        for (int kt = 4; kt < 12; kt++) {
            int rA = (mr + fg) * AST + 8 * kt + fq;
            int rB = rA + 8 * AST;
            unsigned Af[12] = {
                sA0[rA], sA0[rB], sA0[rA + 4], sA0[rB + 4],
                sA1[rA], sA1[rB], sA1[rA + 4], sA1[rB + 4],
                sA2[rA], sA2[rB], sA2[rA + 4], sA2[rB + 4] };
            tile6(aL0a, aL0b, Af, sBhi, fpm, fpl, kt, fg, fq, wn);
            tile6(aL1a, aL1b, Af, sBhi, fpm, fpl, kt + 8, fg, fq, wn);
        }
        #pragma unroll 2
        for (int kt = 12; kt < 20; kt++) {
            int rA = (mr + fg) * AST + 8 * kt + fq;
            int rB = rA + 8 * AST;
            unsigned Af[12] = {
                sA0[rA], sA0[rB], sA0[rA + 4], sA0[rB + 4],
                sA1[rA], sA1[rB], sA1[rA + 4], sA1[rB + 4],
                sA2[rA], sA2[rB], sA2[rA + 4], sA2[rB + 4] };
            tile6(aL1a, aL1b, Af, sBhi, fpm, fpl, kt + 8, fg, fq, wn);
        }

        // updates + publish (warp-local; no CTA sync needed)
        cell_update(aL1a, b1a, odd, c1a, h1a, &g_hbuf[ppar][1][grp][ra][ja]);
        cell_update(aL1b, b1b, odd, c1b, h1b, &g_hbuf[ppar][1][grp][ra][jb]);
        cell_update(aL0a, b0a, odd, c0a, h0a, &g_hbuf[ppar][0][grp][ra][ja]);
        cell_update(aL0b, b0b, odd, c0b, h0b, &g_hbuf[ppar][0][grp][ra][jb]);
        __threadfence();
        __syncthreads();
        phase++;
        if (tid == 0) atomicAdd(&g_ctr[grp], 1);
        // stage x_{t+2} (overlaps barrier skew); skip when out of range
        if (t + 2 < T_STEPS) {
            for (int e = tid; e < 2048; e += NTHR) {
                int r = e >> 5, kp = e & 31;
                const float2 xv = *(const float2*)&x_in[((long)(t + 2) * BATCH + brow0 + r) * SEG + 2 * kp];
                float x0, x1, x2, y0, y1, y2;
                split3(xv.x, x0, x1, x2);
                split3(xv.y, y0, y1, y2);
                sA0[r * AST + kp] = pack_bf(x0, y0);
                sA1[r * AST + kp] = pack_bf(x1, y1);
                sA2[r * AST + kp] = pack_bf(x2, y2);
            }
        }
        if (tid == 0) {
            while (*(volatile int*)&g_ctr[grp] < phase * PSLC) __nanosleep(64);
        }
        __syncthreads();
    }

    // =================== epilogue: layer 1, step 255 ===================
    {
        const int gpar = (T_STEPS - 1) & 1;   // = 1
        for (int e = tid; e < 4096; e += NTHR) {
            int r = e >> 6, m = e & 63;
            uint4 q0 = __ldcg((const uint4*)&g_hbuf[gpar][0][grp][r][2 * m]);
            sA0[r * AST + 32 + m] = (q0.z & 0xffff0000u) | (q0.x >> 16);
            sA1[r * AST + 32 + m] = ((q0.z & 0xffffu) << 16) | (q0.x & 0xffffu);
            sA2[r * AST + 32 + m] = ((q0.w & 0xffffu) << 16) | (q0.y & 0xffffu);
            uint4 q1 = __ldcg((const uint4*)&g_hbuf[gpar][1][grp][r][2 * m]);
            sA0[r * AST + 96 + m] = (q1.z & 0xffff0000u) | (q1.x >> 16);
            sA1[r * AST + 96 + m] = ((q1.z & 0xffffu) << 16) | (q1.x & 0xffffu);
            sA2[r * AST + 96 + m] = ((q1.w & 0xffffu) << 16) | (q1.y & 0xffffu);
        }
        __syncthreads();
        float a0[4] = {0, 0, 0, 0}, a1[4] = {0, 0, 0, 0};
        #pragma unroll 2
        for (int kt = 4; kt < 20; kt++) {
            int rA = (mr + fg) * AST + 8 * kt + fq;
            int rB = rA + 8 * AST;
            unsigned Af[12] = {
                sA0[rA], sA0[rB], sA0[rA + 4], sA0[rB + 4],
                sA1[rA], sA1[rB], sA1[rA + 4], sA1[rB + 4],
                sA2[rA], sA2[rB], sA2[rA + 4], sA2[rB + 4] };
            tile6(a0, a1, Af, sBhi, fpm, fpl, kt + 8, fg, fq, wn);
        }
        cell_update(a0, b1a, odd, c1a, h1a, &g_hbuf[0][1][grp][ra][ja]);
        cell_update(a1, b1b, odd, c1b, h1b, &g_hbuf[0][1][grp][ra][jb]);
    }
    __threadfence();
    __syncthreads();
    phase++;
    if (tid == 0) {
        atomicAdd(&g_ctr[grp], 1);
        while (*(volatile int*)&g_ctr[grp] < phase * PSLC) __nanosleep(64);
    }
    __syncthreads();

    // ---------------- outputs ----------------
    const int OH = BATCH;
    const int OC = BATCH + 2 * BH;
    {
        int b = brow0 + ra;
        out[OH + 0 * BH + b * HID + ja] = h0a;
        out[OH + 0 * BH + b * HID + jb] = h0b;
        out[OH + 1 * BH + b * HID + ja] = h1a;
        out[OH + 1 * BH + b * HID + jb] = h1b;
        out[OC + 0 * BH + b * HID + ja] = c0a;
        out[OC + 0 * BH + b * HID + jb] = c0b;
        out[OC + 1 * BH + b * HID + ja] = c1a;
        out[OC + 1 * BH + b * HID + jb] = c1b;
    }

    if (js == 0 && tid < GRP_ROWS) {
        int r = tid;
        float s = 0.f;
        #pragma unroll 8
        for (int m = 0; m < HID; m++) {
            uint2 pk = __ldcg(&g_hbuf[0][1][grp][r][m]);
            float hv = __bfloat162float(__ushort_as_bfloat16((unsigned short)(pk.x >> 16)))
                     + __bfloat162float(__ushort_as_bfloat16((unsigned short)(pk.x & 0xffffu)))
                     + __bfloat162float(__ushort_as_bfloat16((unsigned short)(pk.y & 0xffffu)));
            s += fmaxf(hv, 0.f) * post_w[m];
        }
        out[brow0 + r] = s + post_b[0];
    }
}

extern "C" void kernel_launch(void* const* d_in, const int* in_sizes, int n_in,
                              void* d_out, int out_size)
{
    const float* x_in   = (const float*)d_in[0];
    const float* h0     = (const float*)d_in[1];
    const float* c0     = (const float*)d_in[2];
    const float* pre_w  = (const float*)d_in[3];
    const float* pre_b  = (const float*)d_in[4];
    const float* w_ih0  = (const float*)d_in[5];
    const float* w_hh0  = (const float*)d_in[6];
    const float* b_ih0  = (const float*)d_in[7];
    const float* b_hh0  = (const float*)d_in[8];
    const float* w_ih1  = (const float*)d_in[9];
    const float* w_hh1  = (const float*)d_in[10];
    const float* b_ih1  = (const float*)d_in[11];
    const float* b_hh1  = (const float*)d_in[12];
    const float* post_w = (const float*)d_in[13];
    const float* post_b = (const float*)d_in[14];
    float* out = (float*)d_out;

    static int attr_set = 0;
    if (!attr_set) {
        cudaFuncSetAttribute(lstm_kernel,
                             cudaFuncAttributeMaxDynamicSharedMemorySize,
                             SMEM_BYTES);
        attr_set = 1;
    }

    prep1_kernel<<<192, 256>>>(pre_w, pre_b, w_ih0, w_hh0, b_ih0, b_hh0,
                               w_ih1, w_hh1, b_ih1, b_hh1);
    prep2_kernel<<<192, 256>>>();
    lstm_kernel<<<NCTA, NTHR, SMEM_BYTES>>>(x_in, h0, c0, post_w, post_b, out);
}